// round 2
// baseline (speedup 1.0000x reference)
#include <cuda_runtime.h>
#include <cstdint>

#define NF      1024
#define NB      256
#define NL      17
#define BATCHN  16384
#define RPB     16          // rows per CTA
#define TPB     512

typedef unsigned long long ull;

// ---------- packed f32x2 helpers ----------
__device__ __forceinline__ ull pk2(float lo, float hi) {
    ull r; asm("mov.b64 %0,{%1,%2};" : "=l"(r) : "f"(lo), "f"(hi)); return r;
}
__device__ __forceinline__ void upk2(ull v, float& a, float& b) {
    asm("mov.b64 {%0,%1},%2;" : "=f"(a), "=f"(b) : "l"(v));
}
__device__ __forceinline__ ull fma2_(ull a, ull b, ull c) {
    ull d; asm("fma.rn.f32x2 %0,%1,%2,%3;" : "=l"(d) : "l"(a), "l"(b), "l"(c)); return d;
}
__device__ __forceinline__ ull mul2_(ull a, ull b) {
    ull d; asm("mul.rn.f32x2 %0,%1,%2;" : "=l"(d) : "l"(a), "l"(b)); return d;
}
__device__ __forceinline__ ull add2_(ull a, ull b) {
    ull d; asm("add.rn.f32x2 %0,%1,%2;" : "=l"(d) : "l"(a), "l"(b)); return d;
}
__device__ __forceinline__ float rsq_(float x) {
    float r; asm("rsqrt.approx.f32 %0,%1;" : "=f"(r) : "f"(x)); return r;
}
__device__ __forceinline__ float lg2_(float x) {
    float r; asm("lg2.approx.f32 %0,%1;" : "=f"(r) : "f"(x)); return r;
}

// ---------- device scratch (no allocation allowed) ----------
// E packed as [l][h(0:j01,1:j23)][e][n] float2 (stored as ull)
__device__ ull   g_Epk[NL * 2 * 4 * NB];
__device__ float g_trace[1];

// ---------- prep: expm of each 4x4 block (scaling & squaring, fp64) ----------
__global__ void prep_expm(const float* __restrict__ vs) {
    int m = blockIdx.x * blockDim.x + threadIdx.x;
    if (m >= NL * NB) return;
    const float* src = vs + m * 16;
    double A[16];
#pragma unroll
    for (int i = 0; i < 16; i++) A[i] = (double)src[i];

    double nrm = 0.0;
#pragma unroll
    for (int r = 0; r < 4; r++) {
        double s = 0.0;
#pragma unroll
        for (int c = 0; c < 4; c++) s += fabs(A[r * 4 + c]);
        if (s > nrm) nrm = s;
    }
    int sc = 0;
    while (nrm > 0.25 && sc < 60) { nrm *= 0.5; sc++; }
    double f = 1.0;
    for (int i = 0; i < sc; i++) f *= 0.5;
#pragma unroll
    for (int i = 0; i < 16; i++) A[i] *= f;

    double X[16], T[16];
#pragma unroll
    for (int i = 0; i < 16; i++) { X[i] = A[i]; T[i] = A[i]; }
    X[0] += 1.0; X[5] += 1.0; X[10] += 1.0; X[15] += 1.0;

    for (int k = 2; k <= 12; k++) {
        double Tn[16];
        double inv = 1.0 / (double)k;
#pragma unroll
        for (int r = 0; r < 4; r++)
#pragma unroll
            for (int c = 0; c < 4; c++) {
                double s = 0.0;
#pragma unroll
                for (int e = 0; e < 4; e++) s += T[r * 4 + e] * A[e * 4 + c];
                Tn[r * 4 + c] = s * inv;
            }
#pragma unroll
        for (int i = 0; i < 16; i++) { T[i] = Tn[i]; X[i] += T[i]; }
    }
    for (int q = 0; q < sc; q++) {
        double Xn[16];
#pragma unroll
        for (int r = 0; r < 4; r++)
#pragma unroll
            for (int c = 0; c < 4; c++) {
                double s = 0.0;
#pragma unroll
                for (int e = 0; e < 4; e++) s += X[r * 4 + e] * X[e * 4 + c];
                Xn[r * 4 + c] = s;
            }
#pragma unroll
        for (int i = 0; i < 16; i++) X[i] = Xn[i];
    }

    int l = m / NB, n = m % NB;
    float2* Ep = (float2*)g_Epk;
#pragma unroll
    for (int e = 0; e < 4; e++) {
        Ep[((l * 2 + 0) * 4 + e) * NB + n] = make_float2((float)X[e * 4 + 0], (float)X[e * 4 + 1]);
        Ep[((l * 2 + 1) * 4 + e) * NB + n] = make_float2((float)X[e * 4 + 2], (float)X[e * 4 + 3]);
    }
}

// ---------- prep: deterministic trace sum ----------
__global__ void prep_trace(const float* __restrict__ vs) {
    __shared__ float red[256];
    int t = threadIdx.x;
    float s = 0.f;
    for (int m = t; m < NL * NB; m += 256) {
        const float* p = vs + m * 16;
        s += p[0] + p[5] + p[10] + p[15];
    }
    red[t] = s;
    __syncthreads();
    for (int o = 128; o > 0; o >>= 1) {
        if (t < o) red[t] += red[t + o];
        __syncthreads();
    }
    if (t == 0) g_trace[0] = red[0];
}

// ---------- main fused flow kernel ----------
extern __shared__ float smem[];

__global__ void __launch_bounds__(TPB, 1) lieflow_main(
    const float* __restrict__ data,
    const float* __restrict__ bs,
    const int*   __restrict__ idxs,
    float*       __restrict__ out,
    int write_logdet)
{
    float* buf0 = smem;
    float* buf1 = smem + RPB * NF;
    float* redm = smem + 2 * RPB * NF;   // RPB * 8 floats

    const int tid = threadIdx.x;
    const int n   = tid & 255;
    const int sub = tid >> 8;            // 0 or 1
    const int rowBase = blockIdx.x * RPB;

    const ull ONE2  = pk2(1.f, 1.f);
    const ull HALF2 = pk2(0.5f, 0.5f);
    const ull NHALF2 = pk2(-0.5f, -0.5f);

    float acc[RPB / 2];
#pragma unroll
    for (int i = 0; i < RPB / 2; i++) acc[i] = 0.f;

    // ---- layer 0: data -> matmul(E0) + b0, stored unpermuted in buf0 ----
    {
        ull E0[4], E1[4];
#pragma unroll
        for (int e = 0; e < 4; e++) {
            E0[e] = g_Epk[((0 * 2 + 0) * 4 + e) * NB + n];
            E1[e] = g_Epk[((0 * 2 + 1) * 4 + e) * NB + n];
        }
        float4 bv = *(const float4*)(bs + 4 * n);
        ull b01 = pk2(bv.x, bv.y), b23 = pk2(bv.z, bv.w);
#pragma unroll 2
        for (int rc = 0; rc < RPB / 2; rc++) {
            int rl = rc * 2 + sub;
            float4 z = *(const float4*)(data + (size_t)(rowBase + rl) * NF + 4 * n);
            ull o01 = b01, o23 = b23, zb;
            zb = pk2(z.x, z.x); o01 = fma2_(zb, E0[0], o01); o23 = fma2_(zb, E1[0], o23);
            zb = pk2(z.y, z.y); o01 = fma2_(zb, E0[1], o01); o23 = fma2_(zb, E1[1], o23);
            zb = pk2(z.z, z.z); o01 = fma2_(zb, E0[2], o01); o23 = fma2_(zb, E1[2], o23);
            zb = pk2(z.w, z.w); o01 = fma2_(zb, E0[3], o01); o23 = fma2_(zb, E1[3], o23);
            float4 o;
            upk2(o01, o.x, o.y); upk2(o23, o.z, o.w);
            *(float4*)(buf0 + rl * NF + 4 * n) = o;
        }
    }
    __syncthreads();

    // ---- layers 1..16: gather(perm) -> bent -> matmul + bias -> store ----
#pragma unroll 1
    for (int l = 1; l < NL; l++) {
        float* src = (l & 1) ? buf0 : buf1;
        float* dst = (l & 1) ? buf1 : buf0;

        ull E0[4], E1[4];
#pragma unroll
        for (int e = 0; e < 4; e++) {
            E0[e] = g_Epk[((l * 2 + 0) * 4 + e) * NB + n];
            E1[e] = g_Epk[((l * 2 + 1) * 4 + e) * NB + n];
        }
        float4 bv = *(const float4*)(bs + l * NF + 4 * n);
        ull b01 = pk2(bv.x, bv.y), b23 = pk2(bv.z, bv.w);
        int4 gi = *(const int4*)(idxs + (l - 1) * NF + 4 * n);

#pragma unroll 2
        for (int rc = 0; rc < RPB / 2; rc++) {
            int rl = rc * 2 + sub;
            const float* sr = src + rl * NF;
            float a0 = sr[gi.x], a1 = sr[gi.y], a2 = sr[gi.z], a3 = sr[gi.w];

            // bent identity (on pre-bent z), packed
            ull Z01 = pk2(a0, a1), Z23 = pk2(a2, a3);
            ull T01 = fma2_(Z01, Z01, ONE2), T23 = fma2_(Z23, Z23, ONE2);
            float t0, t1, t2, t3;
            upk2(T01, t0, t1); upk2(T23, t2, t3);
            ull R01 = pk2(rsq_(t0), rsq_(t1)), R23 = pk2(rsq_(t2), rsq_(t3));
            ull S01 = mul2_(T01, R01), S23 = mul2_(T23, R23);   // sqrt(z^2+1)
            ull U01 = mul2_(Z01, R01), U23 = mul2_(Z23, R23);   // z/s
            ull D01 = fma2_(HALF2, U01, ONE2), D23 = fma2_(HALF2, U23, ONE2); // z/(2s)+1
            ull P = mul2_(D01, D23);
            float p0, p1; upk2(P, p0, p1);
            acc[rc] += lg2_(p0 * p1);                           // chunked log
            ull Zn01 = add2_(fma2_(HALF2, S01, Z01), NHALF2);   // z + (s-1)/2
            ull Zn23 = add2_(fma2_(HALF2, S23, Z23), NHALF2);

            // 4x4 block matmul (row-vector * E) + bias
            float z0, z1, z2, z3;
            upk2(Zn01, z0, z1); upk2(Zn23, z2, z3);
            ull o01 = b01, o23 = b23, zb;
            zb = pk2(z0, z0); o01 = fma2_(zb, E0[0], o01); o23 = fma2_(zb, E1[0], o23);
            zb = pk2(z1, z1); o01 = fma2_(zb, E0[1], o01); o23 = fma2_(zb, E1[1], o23);
            zb = pk2(z2, z2); o01 = fma2_(zb, E0[2], o01); o23 = fma2_(zb, E1[2], o23);
            zb = pk2(z3, z3); o01 = fma2_(zb, E0[3], o01); o23 = fma2_(zb, E1[3], o23);
            float4 o;
            upk2(o01, o.x, o.y); upk2(o23, o.z, o.w);
            *(float4*)(dst + rl * NF + 4 * n) = o;
        }
        __syncthreads();
    }

    // ---- final permutation (idx[16]) + coalesced global write (from buf0) ----
    {
        int4 gi = *(const int4*)(idxs + (NL - 1) * NF + 4 * n);
#pragma unroll 2
        for (int rc = 0; rc < RPB / 2; rc++) {
            int rl = rc * 2 + sub;
            const float* sr = buf0 + rl * NF;
            float4 o;
            o.x = sr[gi.x]; o.y = sr[gi.y]; o.z = sr[gi.z]; o.w = sr[gi.w];
            *(float4*)(out + (size_t)(rowBase + rl) * NF + 4 * n) = o;
        }
    }

    // ---- logdet reduction ----
    __syncthreads();
    const int wid = tid >> 5, lane = tid & 31;
#pragma unroll
    for (int rc = 0; rc < RPB / 2; rc++) {
        float v = acc[rc];
#pragma unroll
        for (int o = 16; o > 0; o >>= 1) v += __shfl_xor_sync(0xffffffffu, v, o);
        if (lane == 0) redm[(rc * 2 + sub) * 8 + (wid & 7)] = v;
    }
    __syncthreads();
    if (write_logdet && tid < RPB) {
        float s = 0.f;
#pragma unroll
        for (int j = 0; j < 8; j++) s += redm[tid * 8 + j];
        out[(size_t)BATCHN * NF + rowBase + tid] =
            -0.6931471805599453f * s - g_trace[0];
    }
}

// ---------- launch ----------
extern "C" void kernel_launch(void* const* d_in, const int* in_sizes, int n_in,
                              void* d_out, int out_size) {
    const float* data = (const float*)d_in[0];
    const float* vs   = (const float*)d_in[1];
    const float* bsp  = (const float*)d_in[2];
    const int*   idxs = (const int*)d_in[3];
    float* out = (float*)d_out;

    const int smem_bytes = (2 * RPB * NF + RPB * 8) * 4;
    cudaFuncSetAttribute(lieflow_main, cudaFuncAttributeMaxDynamicSharedMemorySize, smem_bytes);

    prep_expm<<<(NL * NB + 255) / 256, 256>>>(vs);
    prep_trace<<<1, 256>>>(vs);

    int write_logdet = (out_size >= BATCHN * NF + BATCHN) ? 1 : 0;
    lieflow_main<<<BATCHN / RPB, TPB, smem_bytes>>>(data, bsp, idxs, out, write_logdet);
}

// round 3
// speedup vs baseline: 1.3957x; 1.3957x over previous
#include <cuda_runtime.h>
#include <cstdint>

#define NF      1024
#define NB      256
#define NL      17
#define BATCHN  16384
#define RPB     8           // rows per CTA
#define TPB     512

typedef unsigned long long ull;

// ---------- packed f32x2 helpers ----------
__device__ __forceinline__ ull pk2(float lo, float hi) {
    ull r; asm("mov.b64 %0,{%1,%2};" : "=l"(r) : "f"(lo), "f"(hi)); return r;
}
__device__ __forceinline__ void upk2(ull v, float& a, float& b) {
    asm("mov.b64 {%0,%1},%2;" : "=f"(a), "=f"(b) : "l"(v));
}
__device__ __forceinline__ ull fma2_(ull a, ull b, ull c) {
    ull d; asm("fma.rn.f32x2 %0,%1,%2,%3;" : "=l"(d) : "l"(a), "l"(b), "l"(c)); return d;
}
__device__ __forceinline__ ull mul2_(ull a, ull b) {
    ull d; asm("mul.rn.f32x2 %0,%1,%2;" : "=l"(d) : "l"(a), "l"(b)); return d;
}
__device__ __forceinline__ ull add2_(ull a, ull b) {
    ull d; asm("add.rn.f32x2 %0,%1,%2;" : "=l"(d) : "l"(a), "l"(b)); return d;
}
__device__ __forceinline__ float rsq_(float x) {
    float r; asm("rsqrt.approx.f32 %0,%1;" : "=f"(r) : "f"(x)); return r;
}
__device__ __forceinline__ float lg2_(float x) {
    float r; asm("lg2.approx.f32 %0,%1;" : "=f"(r) : "f"(x)); return r;
}

// ---------- device scratch (no allocation allowed) ----------
// E packed as [l][h(0:j01,1:j23)][e][n] float2 (stored as ull)
__device__ ull   g_Epk[NL * 2 * 4 * NB];
__device__ float g_trace[1];

// ---------- prep: expm of each 4x4 block (fp32 scaling & squaring) ----------
__global__ void prep_expm(const float* __restrict__ vs) {
    int m = blockIdx.x * blockDim.x + threadIdx.x;
    if (m >= NL * NB) return;
    const float* src = vs + m * 16;
    float A[16];
#pragma unroll
    for (int i = 0; i < 16; i++) A[i] = src[i];

    // infinity norm
    float nrm = 0.f;
#pragma unroll
    for (int r = 0; r < 4; r++) {
        float s = fabsf(A[r * 4 + 0]) + fabsf(A[r * 4 + 1]) +
                  fabsf(A[r * 4 + 2]) + fabsf(A[r * 4 + 3]);
        nrm = fmaxf(nrm, s);
    }
    int sc = 0;
    while (nrm > 0.25f && sc < 40) { nrm *= 0.5f; sc++; }
    float f = 1.f;
    for (int i = 0; i < sc; i++) f *= 0.5f;
#pragma unroll
    for (int i = 0; i < 16; i++) A[i] *= f;

    // order-9 Taylor: X = I + A + A^2/2! + ... + A^9/9!
    float X[16], T[16];
#pragma unroll
    for (int i = 0; i < 16; i++) { X[i] = A[i]; T[i] = A[i]; }
    X[0] += 1.f; X[5] += 1.f; X[10] += 1.f; X[15] += 1.f;

#pragma unroll 1
    for (int k = 2; k <= 9; k++) {
        float Tn[16];
        float inv = 1.f / (float)k;
#pragma unroll
        for (int r = 0; r < 4; r++)
#pragma unroll
            for (int c = 0; c < 4; c++) {
                float s = T[r * 4 + 0] * A[0 * 4 + c];
                s = fmaf(T[r * 4 + 1], A[1 * 4 + c], s);
                s = fmaf(T[r * 4 + 2], A[2 * 4 + c], s);
                s = fmaf(T[r * 4 + 3], A[3 * 4 + c], s);
                Tn[r * 4 + c] = s * inv;
            }
#pragma unroll
        for (int i = 0; i < 16; i++) { T[i] = Tn[i]; X[i] += T[i]; }
    }
    // repeated squaring
#pragma unroll 1
    for (int q = 0; q < sc; q++) {
        float Xn[16];
#pragma unroll
        for (int r = 0; r < 4; r++)
#pragma unroll
            for (int c = 0; c < 4; c++) {
                float s = X[r * 4 + 0] * X[0 * 4 + c];
                s = fmaf(X[r * 4 + 1], X[1 * 4 + c], s);
                s = fmaf(X[r * 4 + 2], X[2 * 4 + c], s);
                s = fmaf(X[r * 4 + 3], X[3 * 4 + c], s);
                Xn[r * 4 + c] = s;
            }
#pragma unroll
        for (int i = 0; i < 16; i++) X[i] = Xn[i];
    }

    int l = m / NB, n = m % NB;
    float2* Ep = (float2*)g_Epk;
#pragma unroll
    for (int e = 0; e < 4; e++) {
        Ep[((l * 2 + 0) * 4 + e) * NB + n] = make_float2(X[e * 4 + 0], X[e * 4 + 1]);
        Ep[((l * 2 + 1) * 4 + e) * NB + n] = make_float2(X[e * 4 + 2], X[e * 4 + 3]);
    }
}

// ---------- prep: deterministic trace sum ----------
__global__ void prep_trace(const float* __restrict__ vs) {
    __shared__ float red[256];
    int t = threadIdx.x;
    float s = 0.f;
    for (int m = t; m < NL * NB; m += 256) {
        const float* p = vs + m * 16;
        s += p[0] + p[5] + p[10] + p[15];
    }
    red[t] = s;
    __syncthreads();
    for (int o = 128; o > 0; o >>= 1) {
        if (t < o) red[t] += red[t + o];
        __syncthreads();
    }
    if (t == 0) g_trace[0] = red[0];
}

// ---------- main fused flow kernel ----------
extern __shared__ float smem[];

__global__ void __launch_bounds__(TPB, 2) lieflow_main(
    const float* __restrict__ data,
    const float* __restrict__ bs,
    const int*   __restrict__ idxs,
    float*       __restrict__ out,
    int write_logdet)
{
    float* buf0 = smem;
    float* buf1 = smem + RPB * NF;
    float* redm = smem + 2 * RPB * NF;   // RPB * 8 floats

    const int tid = threadIdx.x;
    const int n   = tid & 255;
    const int sub = tid >> 8;            // 0 or 1
    const int rowBase = blockIdx.x * RPB;

    const ull ONE2  = pk2(1.f, 1.f);
    const ull HALF2 = pk2(0.5f, 0.5f);
    const ull NHALF2 = pk2(-0.5f, -0.5f);

    float acc[RPB / 2];
#pragma unroll
    for (int i = 0; i < RPB / 2; i++) acc[i] = 0.f;

    // ---- layer 0: data -> matmul(E0) + b0, stored unpermuted in buf0 ----
    {
        ull E0[4], E1[4];
#pragma unroll
        for (int e = 0; e < 4; e++) {
            E0[e] = g_Epk[((0 * 2 + 0) * 4 + e) * NB + n];
            E1[e] = g_Epk[((0 * 2 + 1) * 4 + e) * NB + n];
        }
        float4 bv = *(const float4*)(bs + 4 * n);
        ull b01 = pk2(bv.x, bv.y), b23 = pk2(bv.z, bv.w);
#pragma unroll
        for (int rc = 0; rc < RPB / 2; rc++) {
            int rl = rc * 2 + sub;
            float4 z = *(const float4*)(data + (size_t)(rowBase + rl) * NF + 4 * n);
            ull o01 = b01, o23 = b23, zb;
            zb = pk2(z.x, z.x); o01 = fma2_(zb, E0[0], o01); o23 = fma2_(zb, E1[0], o23);
            zb = pk2(z.y, z.y); o01 = fma2_(zb, E0[1], o01); o23 = fma2_(zb, E1[1], o23);
            zb = pk2(z.z, z.z); o01 = fma2_(zb, E0[2], o01); o23 = fma2_(zb, E1[2], o23);
            zb = pk2(z.w, z.w); o01 = fma2_(zb, E0[3], o01); o23 = fma2_(zb, E1[3], o23);
            float4 o;
            upk2(o01, o.x, o.y); upk2(o23, o.z, o.w);
            *(float4*)(buf0 + rl * NF + 4 * n) = o;
        }
    }
    __syncthreads();

    // ---- layers 1..16: gather(perm) -> bent -> matmul + bias -> store ----
#pragma unroll 1
    for (int l = 1; l < NL; l++) {
        float* src = (l & 1) ? buf0 : buf1;
        float* dst = (l & 1) ? buf1 : buf0;

        ull E0[4], E1[4];
#pragma unroll
        for (int e = 0; e < 4; e++) {
            E0[e] = g_Epk[((l * 2 + 0) * 4 + e) * NB + n];
            E1[e] = g_Epk[((l * 2 + 1) * 4 + e) * NB + n];
        }
        float4 bv = *(const float4*)(bs + l * NF + 4 * n);
        ull b01 = pk2(bv.x, bv.y), b23 = pk2(bv.z, bv.w);
        int4 gi = *(const int4*)(idxs + (l - 1) * NF + 4 * n);

#pragma unroll
        for (int rc = 0; rc < RPB / 2; rc++) {
            int rl = rc * 2 + sub;
            const float* sr = src + rl * NF;
            float a0 = sr[gi.x], a1 = sr[gi.y], a2 = sr[gi.z], a3 = sr[gi.w];

            // bent identity (on pre-bent z), packed
            ull Z01 = pk2(a0, a1), Z23 = pk2(a2, a3);
            ull T01 = fma2_(Z01, Z01, ONE2), T23 = fma2_(Z23, Z23, ONE2);
            float t0, t1, t2, t3;
            upk2(T01, t0, t1); upk2(T23, t2, t3);
            ull R01 = pk2(rsq_(t0), rsq_(t1)), R23 = pk2(rsq_(t2), rsq_(t3));
            ull S01 = mul2_(T01, R01), S23 = mul2_(T23, R23);   // sqrt(z^2+1)
            ull U01 = mul2_(Z01, R01), U23 = mul2_(Z23, R23);   // z/s
            ull D01 = fma2_(HALF2, U01, ONE2), D23 = fma2_(HALF2, U23, ONE2); // z/(2s)+1
            ull P = mul2_(D01, D23);
            float p0, p1; upk2(P, p0, p1);
            acc[rc] += lg2_(p0 * p1);                           // chunked log
            ull Zn01 = add2_(fma2_(HALF2, S01, Z01), NHALF2);   // z + (s-1)/2
            ull Zn23 = add2_(fma2_(HALF2, S23, Z23), NHALF2);

            // 4x4 block matmul (row-vector * E) + bias
            float z0, z1, z2, z3;
            upk2(Zn01, z0, z1); upk2(Zn23, z2, z3);
            ull o01 = b01, o23 = b23, zb;
            zb = pk2(z0, z0); o01 = fma2_(zb, E0[0], o01); o23 = fma2_(zb, E1[0], o23);
            zb = pk2(z1, z1); o01 = fma2_(zb, E0[1], o01); o23 = fma2_(zb, E1[1], o23);
            zb = pk2(z2, z2); o01 = fma2_(zb, E0[2], o01); o23 = fma2_(zb, E1[2], o23);
            zb = pk2(z3, z3); o01 = fma2_(zb, E0[3], o01); o23 = fma2_(zb, E1[3], o23);
            float4 o;
            upk2(o01, o.x, o.y); upk2(o23, o.z, o.w);
            *(float4*)(dst + rl * NF + 4 * n) = o;
        }
        __syncthreads();
    }

    // ---- final permutation (idx[16]) + coalesced global write (from buf0) ----
    {
        int4 gi = *(const int4*)(idxs + (NL - 1) * NF + 4 * n);
#pragma unroll
        for (int rc = 0; rc < RPB / 2; rc++) {
            int rl = rc * 2 + sub;
            const float* sr = buf0 + rl * NF;
            float4 o;
            o.x = sr[gi.x]; o.y = sr[gi.y]; o.z = sr[gi.z]; o.w = sr[gi.w];
            *(float4*)(out + (size_t)(rowBase + rl) * NF + 4 * n) = o;
        }
    }

    // ---- logdet reduction ----
    __syncthreads();
    const int wid = tid >> 5, lane = tid & 31;
#pragma unroll
    for (int rc = 0; rc < RPB / 2; rc++) {
        float v = acc[rc];
#pragma unroll
        for (int o = 16; o > 0; o >>= 1) v += __shfl_xor_sync(0xffffffffu, v, o);
        if (lane == 0) redm[(rc * 2 + sub) * 8 + (wid & 7)] = v;
    }
    __syncthreads();
    if (write_logdet && tid < RPB) {
        float s = 0.f;
#pragma unroll
        for (int j = 0; j < 8; j++) s += redm[tid * 8 + j];
        out[(size_t)BATCHN * NF + rowBase + tid] =
            -0.6931471805599453f * s - g_trace[0];
    }
}

// ---------- launch ----------
extern "C" void kernel_launch(void* const* d_in, const int* in_sizes, int n_in,
                              void* d_out, int out_size) {
    const float* data = (const float*)d_in[0];
    const float* vs   = (const float*)d_in[1];
    const float* bsp  = (const float*)d_in[2];
    const int*   idxs = (const int*)d_in[3];
    float* out = (float*)d_out;

    const int smem_bytes = (2 * RPB * NF + RPB * 8) * 4;
    cudaFuncSetAttribute(lieflow_main, cudaFuncAttributeMaxDynamicSharedMemorySize, smem_bytes);

    prep_expm<<<(NL * NB + 255) / 256, 256>>>(vs);
    prep_trace<<<1, 256>>>(vs);

    int write_logdet = (out_size >= BATCHN * NF + BATCHN) ? 1 : 0;
    lieflow_main<<<BATCHN / RPB, TPB, smem_bytes>>>(data, bsp, idxs, out, write_logdet);
}

// round 7
// speedup vs baseline: 1.5315x; 1.0972x over previous
#include <cuda_runtime.h>
#include <cstdint>

#define NF      1024
#define NB      256
#define NL      17
#define BATCHN  16384
#define RPB     4           // rows per CTA
#define TPB     256

typedef unsigned long long ull;

// ---------- packed f32x2 helpers ----------
__device__ __forceinline__ ull pk2(float lo, float hi) {
    ull r; asm("mov.b64 %0,{%1,%2};" : "=l"(r) : "f"(lo), "f"(hi)); return r;
}
__device__ __forceinline__ void upk2(ull v, float& a, float& b) {
    asm("mov.b64 {%0,%1},%2;" : "=f"(a), "=f"(b) : "l"(v));
}
__device__ __forceinline__ ull fma2_(ull a, ull b, ull c) {
    ull d; asm("fma.rn.f32x2 %0,%1,%2,%3;" : "=l"(d) : "l"(a), "l"(b), "l"(c)); return d;
}
__device__ __forceinline__ ull mul2_(ull a, ull b) {
    ull d; asm("mul.rn.f32x2 %0,%1,%2;" : "=l"(d) : "l"(a), "l"(b)); return d;
}
__device__ __forceinline__ ull add2_(ull a, ull b) {
    ull d; asm("add.rn.f32x2 %0,%1,%2;" : "=l"(d) : "l"(a), "l"(b)); return d;
}
__device__ __forceinline__ float rsq_(float x) {
    float r; asm("rsqrt.approx.f32 %0,%1;" : "=f"(r) : "f"(x)); return r;
}
__device__ __forceinline__ float lg2_(float x) {
    float r; asm("lg2.approx.f32 %0,%1;" : "=f"(r) : "f"(x)); return r;
}

// ---------- device scratch (no allocation allowed) ----------
// E packed as [l][h(0:j01,1:j23)][e][n] float2 (stored as ull)
__device__ ull   g_Epk[NL * 2 * 4 * NB];
__device__ float g_trace[1];

// ---------- prep: expm of each 4x4 block (fp32 scaling & squaring) ----------
__global__ void prep_expm(const float* __restrict__ vs) {
    int m = blockIdx.x * blockDim.x + threadIdx.x;
    if (m >= NL * NB) return;
    const float* src = vs + m * 16;
    float A[16];
#pragma unroll
    for (int i = 0; i < 16; i++) A[i] = src[i];

    float nrm = 0.f;
#pragma unroll
    for (int r = 0; r < 4; r++) {
        float s = fabsf(A[r * 4 + 0]) + fabsf(A[r * 4 + 1]) +
                  fabsf(A[r * 4 + 2]) + fabsf(A[r * 4 + 3]);
        nrm = fmaxf(nrm, s);
    }
    int sc = 0;
    while (nrm > 0.25f && sc < 40) { nrm *= 0.5f; sc++; }
    float f = 1.f;
    for (int i = 0; i < sc; i++) f *= 0.5f;
#pragma unroll
    for (int i = 0; i < 16; i++) A[i] *= f;

    // order-9 Taylor
    float X[16], T[16];
#pragma unroll
    for (int i = 0; i < 16; i++) { X[i] = A[i]; T[i] = A[i]; }
    X[0] += 1.f; X[5] += 1.f; X[10] += 1.f; X[15] += 1.f;

#pragma unroll 1
    for (int k = 2; k <= 9; k++) {
        float Tn[16];
        float inv = 1.f / (float)k;
#pragma unroll
        for (int r = 0; r < 4; r++)
#pragma unroll
            for (int c = 0; c < 4; c++) {
                float s = T[r * 4 + 0] * A[0 * 4 + c];
                s = fmaf(T[r * 4 + 1], A[1 * 4 + c], s);
                s = fmaf(T[r * 4 + 2], A[2 * 4 + c], s);
                s = fmaf(T[r * 4 + 3], A[3 * 4 + c], s);
                Tn[r * 4 + c] = s * inv;
            }
#pragma unroll
        for (int i = 0; i < 16; i++) { T[i] = Tn[i]; X[i] += T[i]; }
    }
#pragma unroll 1
    for (int q = 0; q < sc; q++) {
        float Xn[16];
#pragma unroll
        for (int r = 0; r < 4; r++)
#pragma unroll
            for (int c = 0; c < 4; c++) {
                float s = X[r * 4 + 0] * X[0 * 4 + c];
                s = fmaf(X[r * 4 + 1], X[1 * 4 + c], s);
                s = fmaf(X[r * 4 + 2], X[2 * 4 + c], s);
                s = fmaf(X[r * 4 + 3], X[3 * 4 + c], s);
                Xn[r * 4 + c] = s;
            }
#pragma unroll
        for (int i = 0; i < 16; i++) X[i] = Xn[i];
    }

    int l = m / NB, n = m % NB;
    float2* Ep = (float2*)g_Epk;
#pragma unroll
    for (int e = 0; e < 4; e++) {
        Ep[((l * 2 + 0) * 4 + e) * NB + n] = make_float2(X[e * 4 + 0], X[e * 4 + 1]);
        Ep[((l * 2 + 1) * 4 + e) * NB + n] = make_float2(X[e * 4 + 2], X[e * 4 + 3]);
    }
}

// ---------- prep: deterministic trace sum ----------
__global__ void prep_trace(const float* __restrict__ vs) {
    __shared__ float red[256];
    int t = threadIdx.x;
    float s = 0.f;
    for (int m = t; m < NL * NB; m += 256) {
        const float* p = vs + m * 16;
        s += p[0] + p[5] + p[10] + p[15];
    }
    red[t] = s;
    __syncthreads();
    for (int o = 128; o > 0; o >>= 1) {
        if (t < o) red[t] += red[t + o];
        __syncthreads();
    }
    if (t == 0) g_trace[0] = red[0];
}

// ---------- main fused flow kernel ----------
extern __shared__ float smem[];

__global__ void __launch_bounds__(TPB, 4) lieflow_main(
    const float* __restrict__ data,
    const float* __restrict__ bs,
    const int*   __restrict__ idxs,
    float*       __restrict__ out,
    int write_logdet)
{
    float* buf0 = smem;
    float* buf1 = smem + RPB * NF;
    float* redm = smem + 2 * RPB * NF;   // RPB * 8 floats

    const int tid = threadIdx.x;         // == feature block n (0..255)
    const int n   = tid;
    const int rowBase = blockIdx.x * RPB;

    const ull ONE2  = pk2(1.f, 1.f);
    const ull HALF2 = pk2(0.5f, 0.5f);
    const ull NHALF2 = pk2(-0.5f, -0.5f);

    // running per-row Jacobian product (64 factors in (0.5,1.5): fp32-safe)
    float accp[RPB];
#pragma unroll
    for (int i = 0; i < RPB; i++) accp[i] = 1.f;

    // ---- layer 0: data -> matmul(E0) + b0, stored unpermuted in buf0 ----
    {
        ull E0[4], E1[4];
#pragma unroll
        for (int e = 0; e < 4; e++) {
            E0[e] = g_Epk[((0 * 2 + 0) * 4 + e) * NB + n];
            E1[e] = g_Epk[((0 * 2 + 1) * 4 + e) * NB + n];
        }
        float4 bv = *(const float4*)(bs + 4 * n);
        ull b01 = pk2(bv.x, bv.y), b23 = pk2(bv.z, bv.w);
#pragma unroll
        for (int rl = 0; rl < RPB; rl++) {
            float4 z = *(const float4*)(data + (size_t)(rowBase + rl) * NF + 4 * n);
            ull o01 = b01, o23 = b23, zb;
            zb = pk2(z.x, z.x); o01 = fma2_(zb, E0[0], o01); o23 = fma2_(zb, E1[0], o23);
            zb = pk2(z.y, z.y); o01 = fma2_(zb, E0[1], o01); o23 = fma2_(zb, E1[1], o23);
            zb = pk2(z.z, z.z); o01 = fma2_(zb, E0[2], o01); o23 = fma2_(zb, E1[2], o23);
            zb = pk2(z.w, z.w); o01 = fma2_(zb, E0[3], o01); o23 = fma2_(zb, E1[3], o23);
            float4 o;
            upk2(o01, o.x, o.y); upk2(o23, o.z, o.w);
            *(float4*)(buf0 + rl * NF + 4 * n) = o;
        }
    }
    __syncthreads();

    // ---- layers 1..16: gather(perm) -> bent -> matmul + bias -> store ----
#pragma unroll 1
    for (int l = 1; l < NL; l++) {
        float* src = (l & 1) ? buf0 : buf1;
        float* dst = (l & 1) ? buf1 : buf0;

        ull E0[4], E1[4];
#pragma unroll
        for (int e = 0; e < 4; e++) {
            E0[e] = g_Epk[((l * 2 + 0) * 4 + e) * NB + n];
            E1[e] = g_Epk[((l * 2 + 1) * 4 + e) * NB + n];
        }
        float4 bv = *(const float4*)(bs + l * NF + 4 * n);
        ull b01 = pk2(bv.x, bv.y), b23 = pk2(bv.z, bv.w);
        int4 gi = *(const int4*)(idxs + (l - 1) * NF + 4 * n);

#pragma unroll
        for (int rl = 0; rl < RPB; rl++) {
            const float* sr = src + rl * NF;
            float a0 = sr[gi.x], a1 = sr[gi.y], a2 = sr[gi.z], a3 = sr[gi.w];

            // bent identity (on pre-bent z), packed
            ull Z01 = pk2(a0, a1), Z23 = pk2(a2, a3);
            ull T01 = fma2_(Z01, Z01, ONE2), T23 = fma2_(Z23, Z23, ONE2);
            float t0, t1, t2, t3;
            upk2(T01, t0, t1); upk2(T23, t2, t3);
            ull R01 = pk2(rsq_(t0), rsq_(t1)), R23 = pk2(rsq_(t2), rsq_(t3));
            ull S01 = mul2_(T01, R01), S23 = mul2_(T23, R23);   // sqrt(z^2+1)
            ull U01 = mul2_(Z01, R01), U23 = mul2_(Z23, R23);   // z/s
            ull D01 = fma2_(HALF2, U01, ONE2), D23 = fma2_(HALF2, U23, ONE2); // z/(2s)+1
            ull P = mul2_(D01, D23);
            float p0, p1; upk2(P, p0, p1);
            accp[rl] *= (p0 * p1);                              // deferred log
            ull Zn01 = add2_(fma2_(HALF2, S01, Z01), NHALF2);   // z + (s-1)/2
            ull Zn23 = add2_(fma2_(HALF2, S23, Z23), NHALF2);

            // 4x4 block matmul (row-vector * E) + bias
            float z0, z1, z2, z3;
            upk2(Zn01, z0, z1); upk2(Zn23, z2, z3);
            ull o01 = b01, o23 = b23, zb;
            zb = pk2(z0, z0); o01 = fma2_(zb, E0[0], o01); o23 = fma2_(zb, E1[0], o23);
            zb = pk2(z1, z1); o01 = fma2_(zb, E0[1], o01); o23 = fma2_(zb, E1[1], o23);
            zb = pk2(z2, z2); o01 = fma2_(zb, E0[2], o01); o23 = fma2_(zb, E1[2], o23);
            zb = pk2(z3, z3); o01 = fma2_(zb, E0[3], o01); o23 = fma2_(zb, E1[3], o23);
            float4 o;
            upk2(o01, o.x, o.y); upk2(o23, o.z, o.w);
            *(float4*)(dst + rl * NF + 4 * n) = o;
        }
        __syncthreads();
    }

    // ---- final permutation (idx[16]) + coalesced global write (from buf0) ----
    {
        int4 gi = *(const int4*)(idxs + (NL - 1) * NF + 4 * n);
#pragma unroll
        for (int rl = 0; rl < RPB; rl++) {
            const float* sr = buf0 + rl * NF;
            float4 o;
            o.x = sr[gi.x]; o.y = sr[gi.y]; o.z = sr[gi.z]; o.w = sr[gi.w];
            *(float4*)(out + (size_t)(rowBase + rl) * NF + 4 * n) = o;
        }
    }

    // ---- logdet reduction (one lg2 per row per thread) ----
    __syncthreads();
    const int wid = tid >> 5, lane = tid & 31;
#pragma unroll
    for (int rl = 0; rl < RPB; rl++) {
        float v = lg2_(accp[rl]);
#pragma unroll
        for (int o = 16; o > 0; o >>= 1) v += __shfl_xor_sync(0xffffffffu, v, o);
        if (lane == 0) redm[rl * 8 + wid] = v;
    }
    __syncthreads();
    if (write_logdet && tid < RPB) {
        float s = 0.f;
#pragma unroll
        for (int j = 0; j < 8; j++) s += redm[tid * 8 + j];
        out[(size_t)BATCHN * NF + rowBase + tid] =
            -0.6931471805599453f * s - g_trace[0];
    }
}

// ---------- launch ----------
extern "C" void kernel_launch(void* const* d_in, const int* in_sizes, int n_in,
                              void* d_out, int out_size) {
    const float* data = (const float*)d_in[0];
    const float* vs   = (const float*)d_in[1];
    const float* bsp  = (const float*)d_in[2];
    const int*   idxs = (const int*)d_in[3];
    float* out = (float*)d_out;

    const int smem_bytes = (2 * RPB * NF + RPB * 8) * 4;
    cudaFuncSetAttribute(lieflow_main, cudaFuncAttributeMaxDynamicSharedMemorySize, smem_bytes);

    prep_expm<<<(NL * NB + 255) / 256, 256>>>(vs);
    prep_trace<<<1, 256>>>(vs);

    int write_logdet = (out_size >= BATCHN * NF + BATCHN) ? 1 : 0;
    lieflow_main<<<BATCHN / RPB, TPB, smem_bytes>>>(data, bsp, idxs, out, write_logdet);
}